// round 3
// baseline (speedup 1.0000x reference)
#include <cuda_runtime.h>
#include <math.h>

#define TN 8
#define TE 8
#define MAXN 20480

// Scratch: na0 = o3_linear(node_attr) and h = o3_linear(norm_gate(node_attr))
__device__ float g_na0[MAXN * 256];
__device__ float g_h[MAXN * 256];

__device__ __forceinline__ float siluf(float x) { return x * (1.f / (1.f + __expf(-x))); }
__device__ __forceinline__ float sspf(float x) {
    float sp = (x > 20.f) ? x : log1pf(__expf(x));
    return sp - 0.6931471805599453f;
}

// o3.Linear: out_s[j] = (sum_u xs[u]*W0[u][j])/8 + b0[j]
//            out_v[j][c] = (sum_u xv[u][c]*W1[u][j])/8
// Thread t (0..15) computes columns 4t..4t+3. xin is smem (256), orow is a global row (256).
__device__ __forceinline__ void o3_linear_dev(
    const float* __restrict__ xin,
    const float* __restrict__ W0, const float* __restrict__ b0,
    const float* __restrict__ W1,
    float* __restrict__ orow, int t)
{
    const float4* W04 = (const float4*)W0;
    float4 acc = make_float4(0.f, 0.f, 0.f, 0.f);
#pragma unroll 4
    for (int u = 0; u < 64; u++) {
        float xs = xin[u];
        float4 wv = W04[u * 16 + t];
        acc.x += xs * wv.x; acc.y += xs * wv.y; acc.z += xs * wv.z; acc.w += xs * wv.w;
    }
    float4 bb = ((const float4*)b0)[t];
    float4 os;
    os.x = acc.x * 0.125f + bb.x;
    os.y = acc.y * 0.125f + bb.y;
    os.z = acc.z * 0.125f + bb.z;
    os.w = acc.w * 0.125f + bb.w;
    ((float4*)orow)[t] = os;

    float a00=0,a01=0,a02=0, a10=0,a11=0,a12=0, a20=0,a21=0,a22=0, a30=0,a31=0,a32=0;
    const float4* W14 = (const float4*)W1;
#pragma unroll 4
    for (int u = 0; u < 64; u++) {
        float4 wv = W14[u * 16 + t];
        float x0 = xin[64 + 3*u], x1 = xin[64 + 3*u + 1], x2 = xin[64 + 3*u + 2];
        a00 += x0 * wv.x; a01 += x1 * wv.x; a02 += x2 * wv.x;
        a10 += x0 * wv.y; a11 += x1 * wv.y; a12 += x2 * wv.y;
        a20 += x0 * wv.z; a21 += x1 * wv.z; a22 += x2 * wv.z;
        a30 += x0 * wv.w; a31 += x1 * wv.w; a32 += x2 * wv.w;
    }
    float* op = orow + 64 + 12 * t;
    op[0]=a00*0.125f; op[1]=a01*0.125f; op[2]=a02*0.125f;
    op[3]=a10*0.125f; op[4]=a11*0.125f; op[5]=a12*0.125f;
    op[6]=a20*0.125f; op[7]=a21*0.125f; op[8]=a22*0.125f;
    op[9]=a30*0.125f; op[10]=a31*0.125f; op[11]=a32*0.125f;
}

// 128x128 dense layer: out[j] = act(sum_k fin[k]*W[k][j] + b[j]); thread t does cols 8t..8t+7.
template <bool SILU>
__device__ __forceinline__ void gemm128_dev(
    const float* __restrict__ fin, const float* __restrict__ W,
    const float* __restrict__ b, float* __restrict__ outp, int t)
{
    const float4* W4 = (const float4*)W;
    float4 a0 = make_float4(0.f,0.f,0.f,0.f), a1 = make_float4(0.f,0.f,0.f,0.f);
#pragma unroll 4
    for (int k = 0; k < 128; k++) {
        float f = fin[k];
        float4 w0 = W4[k * 32 + 2 * t];
        float4 w1 = W4[k * 32 + 2 * t + 1];
        a0.x += f * w0.x; a0.y += f * w0.y; a0.z += f * w0.z; a0.w += f * w0.w;
        a1.x += f * w1.x; a1.y += f * w1.y; a1.z += f * w1.z; a1.w += f * w1.w;
    }
    float4 b0 = ((const float4*)b)[2 * t], b1 = ((const float4*)b)[2 * t + 1];
    float r[8];
    r[0]=a0.x+b0.x; r[1]=a0.y+b0.y; r[2]=a0.z+b0.z; r[3]=a0.w+b0.w;
    r[4]=a1.x+b1.x; r[5]=a1.y+b1.y; r[6]=a1.z+b1.z; r[7]=a1.w+b1.w;
#pragma unroll
    for (int i = 0; i < 8; i++) {
        float v = r[i];
        if (SILU) v = siluf(v);
        outp[8 * t + i] = v;
    }
}

// ---------------- Node kernel: na0 and h ----------------
// Per-node smem: x[256] f0[128] tt[128] gg[128] hng[256] = 896 floats; TN=8 -> 28672 B static
__global__ void node_kernel(
    const float* __restrict__ na,
    const float* __restrict__ Wi0, const float* __restrict__ bi0, const float* __restrict__ Wi1,
    const float* __restrict__ gpW1, const float* __restrict__ gpb1,
    const float* __restrict__ gpW2, const float* __restrict__ gpb2,
    const float* __restrict__ Wn0, const float* __restrict__ bn0, const float* __restrict__ Wn1,
    int N)
{
    __shared__ float sm[TN * 896];
    const int t = threadIdx.x & 15;
    const int ln = threadIdx.x >> 4;
    const int node = blockIdx.x * TN + ln;
    const bool valid = node < N;
    float* x = sm + ln * 896;
    float* f0 = x + 256;
    float* tt = x + 384;
    float* gg = x + 512;
    float* hng = x + 640;

    if (valid) {
        float4* d4 = (float4*)x;
        const float4* s4 = (const float4*)(na + (size_t)node * 256);
#pragma unroll
        for (int i = t; i < 64; i += 16) d4[i] = s4[i];
    }
    __syncthreads();

    if (valid) {
        // invariant branch input: na0 = o3_linear(node_attr)
        o3_linear_dev(x, Wi0, bi0, Wi1, g_na0 + (size_t)node * 256, t);
        // norm_gate features f0 = [s, |v|]
#pragma unroll
        for (int k = 0; k < 4; k++) f0[4 * t + k] = x[4 * t + k];
#pragma unroll
        for (int k = 0; k < 4; k++) {
            int i = 4 * t + k;
            float a = x[64 + 3*i], b = x[64 + 3*i + 1], c = x[64 + 3*i + 2];
            f0[64 + i] = sqrtf(a*a + b*b + c*c);
        }
    }
    __syncthreads();
    if (valid) gemm128_dev<true>(f0, gpW1, gpb1, tt, t);
    __syncthreads();
    if (valid) gemm128_dev<false>(tt, gpW2, gpb2, gg, t);
    __syncthreads();
    if (valid) {
#pragma unroll
        for (int k = 0; k < 4; k++) { int j = 4 * t + k; hng[j] = gg[j]; }
#pragma unroll
        for (int k = 0; k < 4; k++) {
            int i = 4 * t + k;
            float gv = gg[64 + i];
            hng[64 + 3*i]     = x[64 + 3*i]     * gv;
            hng[64 + 3*i + 1] = x[64 + 3*i + 1] * gv;
            hng[64 + 3*i + 2] = x[64 + 3*i + 2] * gv;
        }
    }
    __syncthreads();
    if (valid) o3_linear_dev(hng, Wn0, bn0, Wn1, g_h + (size_t)node * 256, t);
}

// ---------------- Edge kernel ----------------
// Per-edge smem floats: ea[32] t8[8] s0[192] u[64] w[320] pv[192] f0[128] tt[128] gg[128] vg[192] = 1384
// TE=8 -> 44288 B static
#define ESTRIDE 1384
__global__ void edge_kernel(
    const float* __restrict__ edge_attr, const float* __restrict__ npa,
    const float* __restrict__ feW1, const float* __restrict__ feW2,
    const float* __restrict__ fsW1, const float* __restrict__ fsb1,
    const float* __restrict__ fsW2, const float* __restrict__ fsb2,
    const float* __restrict__ gW1, const float* __restrict__ gb1,
    const float* __restrict__ gW2, const float* __restrict__ gb2,
    const float* __restrict__ Wo0, const float* __restrict__ bo0, const float* __restrict__ Wo1,
    const int* __restrict__ ei, float* __restrict__ out, int E)
{
    __shared__ float sm[TE * ESTRIDE];
    const int t = threadIdx.x & 15;
    const int le = threadIdx.x >> 4;
    const int e = blockIdx.x * TE + le;
    const bool valid = e < E;

    float* base = sm + le * ESTRIDE;
    float* ea = base;          // 32
    float* t8 = base + 32;     // 8
    float* s0 = base + 40;     // 192
    float* u  = base + 232;    // 64
    float* w  = base + 296;    // 320
    float* pv = base + 616;    // 192
    float* f0 = base + 808;    // 128
    float* tt = base + 936;    // 128
    float* gg = base + 1064;   // 128
    float* vg = base + 1192;   // 192

    int dst = 0, src = 0;
    if (valid) { dst = ei[e]; src = ei[E + e]; }
    const float* nd = g_na0 + (size_t)dst * 256;
    const float* ns = g_na0 + (size_t)src * 256;

    if (valid) {
        ((float2*)ea)[t] = ((const float2*)(edge_attr + (size_t)e * 32))[t];
        ((float4*)s0)[t]        = ((const float4*)nd)[t];   // s_d
        ((float4*)(s0 + 64))[t] = ((const float4*)ns)[t];   // s_s
#pragma unroll
        for (int k = 0; k < 4; k++) {                       // InnerProduct / 3
            int i = 4 * t + k;
            float a = nd[64 + 3*i] * ns[64 + 3*i]
                    + nd[64 + 3*i + 1] * ns[64 + 3*i + 1]
                    + nd[64 + 3*i + 2] * ns[64 + 3*i + 2];
            s0[128 + i] = a * (1.f / 3.f);
        }
    }
    __syncthreads();

    if (valid) {
        if (t < 8) {  // fe hidden layer: ssp(edge_attr @ feW1 / sqrt(32))
            float a = 0.f;
#pragma unroll 4
            for (int k = 0; k < 32; k++) a += ea[k] * feW1[k * 8 + t];
            t8[t] = sspf(a * 0.17677669529663687f);
        }
        // u = silu(s0 @ fsW1 + fsb1), cols 4t..4t+3
        float4 acc = make_float4(0.f,0.f,0.f,0.f);
        const float4* W = (const float4*)fsW1;
#pragma unroll 4
        for (int k = 0; k < 192; k++) {
            float s = s0[k];
            float4 wv = W[k * 16 + t];
            acc.x += s * wv.x; acc.y += s * wv.y; acc.z += s * wv.z; acc.w += s * wv.w;
        }
        float4 bb = ((const float4*)fsb1)[t];
        u[4*t]   = siluf(acc.x + bb.x);
        u[4*t+1] = siluf(acc.y + bb.y);
        u[4*t+2] = siluf(acc.z + bb.z);
        u[4*t+3] = siluf(acc.w + bb.w);
    }
    __syncthreads();

    if (valid) {
        // w = (t8 @ feW2 / sqrt(8)) * (u @ fsW2 + fsb2); 320 cols = 5 groups of 64
        const float4* We = (const float4*)feW2;   // [8,320]
        const float4* Ws = (const float4*)fsW2;   // [64,320]
        const float4* Bs = (const float4*)fsb2;
        float t8r[8];
#pragma unroll
        for (int i = 0; i < 8; i++) t8r[i] = t8[i];
#pragma unroll
        for (int p = 0; p < 5; p++) {
            int col4 = p * 16 + t;
            float4 fe = make_float4(0.f,0.f,0.f,0.f);
#pragma unroll
            for (int i = 0; i < 8; i++) {
                float4 wv = We[i * 80 + col4];
                fe.x += t8r[i]*wv.x; fe.y += t8r[i]*wv.y; fe.z += t8r[i]*wv.z; fe.w += t8r[i]*wv.w;
            }
            float4 fs = Bs[col4];
#pragma unroll 4
            for (int k = 0; k < 64; k++) {
                float uu = u[k];
                float4 wv = Ws[k * 80 + col4];
                fs.x += uu*wv.x; fs.y += uu*wv.y; fs.z += uu*wv.z; fs.w += uu*wv.w;
            }
            const float isq8 = 0.3535533905932738f;
            float4 wr;
            wr.x = fe.x * isq8 * fs.x;
            wr.y = fe.y * isq8 * fs.y;
            wr.z = fe.z * isq8 * fs.z;
            wr.w = fe.w * isq8 * fs.w;
            ((float4*)w)[p * 16 + t] = wr;
        }
    }
    __syncthreads();

    if (valid) {
        // tensor product: x = h[src], y = h[dst]
        const float C0 = 0.4472135954999579f;   // sqrt(1/5)
        const float C1 = 0.7745966692414834f;   // sqrt(3/5)
        const float IS3 = 0.5773502691896258f;  // 1/sqrt(3)
        const float IS6 = 0.4082482904638630f;  // 1/sqrt(6)
        const float* hs = g_h + (size_t)src * 256;
        const float* hd = g_h + (size_t)dst * 256;
#pragma unroll
        for (int k = 0; k < 4; k++) {
            int i = 4 * t + k;
            float xs = hs[i], ys = hd[i];
            float xv0 = hs[64+3*i], xv1 = hs[64+3*i+1], xv2 = hs[64+3*i+2];
            float yv0 = hd[64+3*i], yv1 = hd[64+3*i+1], yv2 = hd[64+3*i+2];
            float ipv = xv0*yv0 + xv1*yv1 + xv2*yv2;
            float psv = C0 * (w[i] * xs * ys + w[192 + i] * ipv * IS3);
            float cx = xv1*yv2 - xv2*yv1;
            float cy = xv2*yv0 - xv0*yv2;
            float cz = xv0*yv1 - xv1*yv0;
            float a011 = w[64 + i]  * IS3 * C1;
            float a101 = w[128 + i] * IS3 * C1;
            float a111 = w[256 + i] * IS6 * C1;
            float p0 = a011 * xs * yv0 + a101 * xv0 * ys + a111 * cx;
            float p1 = a011 * xs * yv1 + a101 * xv1 * ys + a111 * cy;
            float p2 = a011 * xs * yv2 + a101 * xv2 * ys + a111 * cz;
            pv[3*i] = p0; pv[3*i+1] = p1; pv[3*i+2] = p2;
            f0[i] = psv;
            f0[64 + i] = sqrtf(p0*p0 + p1*p1 + p2*p2);
        }
    }
    __syncthreads();
    if (valid) gemm128_dev<true>(f0, gW1, gb1, tt, t);
    __syncthreads();
    if (valid) gemm128_dev<false>(tt, gW2, gb2, gg, t);
    __syncthreads();
    if (valid) {
#pragma unroll
        for (int k = 0; k < 4; k++) {
            int i = 4 * t + k;
            float gv = gg[64 + i];
            vg[3*i]   = pv[3*i]   * gv;
            vg[3*i+1] = pv[3*i+1] * gv;
            vg[3*i+2] = pv[3*i+2] * gv;
        }
    }
    __syncthreads();
    if (valid) {
        // final o3_linear + residual
        const float4* W04 = (const float4*)Wo0;
        float4 acc = make_float4(0.f,0.f,0.f,0.f);
#pragma unroll 4
        for (int uu = 0; uu < 64; uu++) {
            float s = gg[uu];
            float4 wv = W04[uu * 16 + t];
            acc.x += s*wv.x; acc.y += s*wv.y; acc.z += s*wv.z; acc.w += s*wv.w;
        }
        float4 bb = ((const float4*)bo0)[t];
        float4 n0 = ((const float4*)(npa + (size_t)e * 256))[t];
        float4 os;
        os.x = acc.x * 0.125f + bb.x + n0.x;
        os.y = acc.y * 0.125f + bb.y + n0.y;
        os.z = acc.z * 0.125f + bb.z + n0.z;
        os.w = acc.w * 0.125f + bb.w + n0.w;
        ((float4*)(out + (size_t)e * 256))[t] = os;

        float a00=0,a01=0,a02=0, a10=0,a11=0,a12=0, a20=0,a21=0,a22=0, a30=0,a31=0,a32=0;
        const float4* W14 = (const float4*)Wo1;
#pragma unroll 4
        for (int uu = 0; uu < 64; uu++) {
            float4 wv = W14[uu * 16 + t];
            float x0 = vg[3*uu], x1 = vg[3*uu+1], x2 = vg[3*uu+2];
            a00 += x0*wv.x; a01 += x1*wv.x; a02 += x2*wv.x;
            a10 += x0*wv.y; a11 += x1*wv.y; a12 += x2*wv.y;
            a20 += x0*wv.z; a21 += x1*wv.z; a22 += x2*wv.z;
            a30 += x0*wv.w; a31 += x1*wv.w; a32 += x2*wv.w;
        }
        float* op = out + (size_t)e * 256 + 64 + 12 * t;
        const float* np = npa + (size_t)e * 256 + 64 + 12 * t;
        op[0]=a00*0.125f+np[0];  op[1]=a01*0.125f+np[1];  op[2]=a02*0.125f+np[2];
        op[3]=a10*0.125f+np[3];  op[4]=a11*0.125f+np[4];  op[5]=a12*0.125f+np[5];
        op[6]=a20*0.125f+np[6];  op[7]=a21*0.125f+np[7];  op[8]=a22*0.125f+np[8];
        op[9]=a30*0.125f+np[9];  op[10]=a31*0.125f+np[10]; op[11]=a32*0.125f+np[11];
    }
}

extern "C" void kernel_launch(void* const* d_in, const int* in_sizes, int n_in,
                              void* d_out, int out_size)
{
    const float* node_attr = (const float*)d_in[0];
    const float* edge_attr = (const float*)d_in[1];
    const float* npa       = (const float*)d_in[2];
    const float* Wi0 = (const float*)d_in[3];
    const float* bi0 = (const float*)d_in[4];
    const float* Wi1 = (const float*)d_in[5];
    const float* gpW1 = (const float*)d_in[6];
    const float* gpb1 = (const float*)d_in[7];
    const float* gpW2 = (const float*)d_in[8];
    const float* gpb2 = (const float*)d_in[9];
    const float* Wn0 = (const float*)d_in[10];
    const float* bn0 = (const float*)d_in[11];
    const float* Wn1 = (const float*)d_in[12];
    const float* feW1 = (const float*)d_in[13];
    const float* feW2 = (const float*)d_in[14];
    const float* fsW1 = (const float*)d_in[15];
    const float* fsb1 = (const float*)d_in[16];
    const float* fsW2 = (const float*)d_in[17];
    const float* fsb2 = (const float*)d_in[18];
    const float* gW1 = (const float*)d_in[19];
    const float* gb1 = (const float*)d_in[20];
    const float* gW2 = (const float*)d_in[21];
    const float* gb2 = (const float*)d_in[22];
    const float* Wo0 = (const float*)d_in[23];
    const float* bo0 = (const float*)d_in[24];
    const float* Wo1 = (const float*)d_in[25];
    const int*   ei  = (const int*)d_in[26];

    int N = in_sizes[0] / 256;
    if (N > MAXN) N = MAXN;   // scratch capacity guard
    int E = in_sizes[26] / 2;
    float* out = (float*)d_out;

    node_kernel<<<(N + TN - 1) / TN, TN * 16>>>(
        node_attr, Wi0, bi0, Wi1, gpW1, gpb1, gpW2, gpb2, Wn0, bn0, Wn1, N);
    edge_kernel<<<(E + TE - 1) / TE, TE * 16>>>(
        edge_attr, npa, feW1, feW2, fsW1, fsb1, fsW2, fsb2,
        gW1, gb1, gW2, gb2, Wo0, bo0, Wo1, ei, out, E);
}

// round 4
// speedup vs baseline: 1.5176x; 1.5176x over previous
#include <cuda_runtime.h>
#include <math.h>

#define MAXN 20480
#define MAXE 122880
#define NPLANE ((size_t)MAXN * 64)
#define EPLANE ((size_t)MAXE * 64)

// ---------------- scratch (__device__, static) ----------------
// node side
__device__ float g_sn  [MAXN * 64];        // scalars of node_attr
__device__ float g_xv  [3 * MAXN * 64];    // vector planes of node_attr
__device__ float g_f0n [MAXN * 128];       // [s, |v|]
__device__ float g_t1  [MAXN * 128];
__device__ float g_g   [MAXN * 128];       // norm_gate MLP out
__device__ float g_hvg [3 * MAXN * 64];    // gated vectors
__device__ float g_na0s[MAXN * 64];
__device__ float g_na0v[3 * MAXN * 64];
__device__ float g_hs  [MAXN * 64];
__device__ float g_hv  [3 * MAXN * 64];
// edge side
__device__ float g_s0  [(size_t)MAXE * 192];
__device__ float g_t8  [(size_t)MAXE * 8];
__device__ float g_u   [(size_t)MAXE * 64];
__device__ float g_fe  [(size_t)MAXE * 320];
__device__ float g_w   [(size_t)MAXE * 320];
__device__ float g_f0e [(size_t)MAXE * 128];
__device__ float g_pv  [3 * (size_t)MAXE * 64];
__device__ float g_t2  [(size_t)MAXE * 128];
__device__ float g_g2  [(size_t)MAXE * 128];
__device__ float g_vg  [3 * (size_t)MAXE * 64];

__device__ __forceinline__ float siluf(float x) { return x * (1.f / (1.f + __expf(-x))); }
__device__ __forceinline__ float sspf(float x) {
    float sp = (x > 20.f) ? x : log1pf(__expf(x));
    return sp - 0.6931471805599453f;
}

// packed fp32x2 FMA (sm_103a)
#define FFMA2(d, a, b) asm("fma.rn.f32x2 %0, %1, %2, %0;" : "+l"(d) : "l"(a), "l"(b))

// ---------------- generic tiled GEMM ----------------
// C[row, n] = epilogue( alpha * sum_k A[row,k] * W[k,n] )
// block tile: 128 rows x 64 cols, BK=32. 256 threads, thread tile 8x4 via f32x2 pairs.
#define BM 128
#define BN 64
#define BK 32
#define AS_LD 132   // padded, 16B-aligned rows
#define WS_LD 136   // duplicated-pair weight rows, 16B-aligned

__global__ void __launch_bounds__(256) gemm_kernel(
    const float* __restrict__ A, int lda, size_t aPlane,
    const float* __restrict__ W, int ldw,
    const float* __restrict__ bias,
    const float* __restrict__ aux, int auxLd, float auxScale,
    const float* __restrict__ res,
    float* __restrict__ out, int outLd, int colStride, int colOff, int zColStep, size_t outPlane,
    int M, int K, float alpha, int act)
{
    __shared__ __align__(16) float As[BK * AS_LD];
    __shared__ __align__(16) float WsD[BK * WS_LD];

    const int z = blockIdx.z;
    A += (size_t)z * aPlane;
    out += (size_t)z * outPlane;
    const int cOff = colOff + z * zColStep;

    const int tid = threadIdx.x;
    const int tx = tid & 15;       // col group: 4 cols
    const int ty = tid >> 4;       // row group: 8 rows
    const int wid = tid >> 5, lane = tid & 31;
    const int rowBase = blockIdx.x * BM;
    const int nBase = blockIdx.y * BN;

    unsigned long long acc[4][4];
#pragma unroll
    for (int p = 0; p < 4; p++)
#pragma unroll
        for (int c = 0; c < 4; c++) acc[p][c] = 0ull;

    for (int k0 = 0; k0 < K; k0 += BK) {
        // fill A tile: As[k][m], warp wid loads 16 rows, lane = k
#pragma unroll 4
        for (int r = 0; r < 16; r++) {
            int mLoc = wid * 16 + r;
            int gRow = rowBase + mLoc;
            float v = 0.f;
            if (gRow < M) v = A[(size_t)gRow * lda + k0 + lane];
            As[lane * AS_LD + mLoc] = v;
        }
        // fill duplicated W tile
        for (int i = tid; i < BK * BN; i += 256) {
            int k = i >> 6, n = i & 63;
            float wv = W[(size_t)(k0 + k) * ldw + nBase + n];
            int o = k * WS_LD + 2 * n;
            WsD[o] = wv; WsD[o + 1] = wv;
        }
        __syncthreads();

#pragma unroll
        for (int k = 0; k < BK; k++) {
            const ulonglong2* ap = (const ulonglong2*)&As[k * AS_LD + ty * 8];
            ulonglong2 a0 = ap[0], a1 = ap[1];                 // row pairs (0,1)(2,3)(4,5)(6,7)
            const ulonglong2* wp = (const ulonglong2*)&WsD[k * WS_LD + tx * 8];
            ulonglong2 w0 = wp[0], w1 = wp[1];                 // dup cols c0,c1,c2,c3
            FFMA2(acc[0][0], a0.x, w0.x); FFMA2(acc[0][1], a0.x, w0.y);
            FFMA2(acc[0][2], a0.x, w1.x); FFMA2(acc[0][3], a0.x, w1.y);
            FFMA2(acc[1][0], a0.y, w0.x); FFMA2(acc[1][1], a0.y, w0.y);
            FFMA2(acc[1][2], a0.y, w1.x); FFMA2(acc[1][3], a0.y, w1.y);
            FFMA2(acc[2][0], a1.x, w0.x); FFMA2(acc[2][1], a1.x, w0.y);
            FFMA2(acc[2][2], a1.x, w1.x); FFMA2(acc[2][3], a1.x, w1.y);
            FFMA2(acc[3][0], a1.y, w0.x); FFMA2(acc[3][1], a1.y, w0.y);
            FFMA2(acc[3][2], a1.y, w1.x); FFMA2(acc[3][3], a1.y, w1.y);
        }
        __syncthreads();
    }

    // epilogue
#pragma unroll
    for (int p = 0; p < 4; p++) {
#pragma unroll
        for (int h = 0; h < 2; h++) {
            int row = rowBase + ty * 8 + 2 * p + h;
            if (row >= M) continue;
#pragma unroll
            for (int c = 0; c < 4; c++) {
                unsigned long long uacc = acc[p][c];
                float v = __uint_as_float(h == 0 ? (unsigned)uacc : (unsigned)(uacc >> 32));
                v *= alpha;
                int nG = nBase + tx * 4 + c;
                if (bias) v += bias[nG];
                if (act == 1) v = siluf(v);
                if (aux) v *= aux[(size_t)row * auxLd + nG] * auxScale;
                size_t oi = (size_t)row * outLd + cOff + (size_t)nG * colStride;
                if (res) v += res[oi];
                out[oi] = v;
            }
        }
    }
}

// ---------------- elementwise / gather kernels ----------------

__global__ void prep_node_kernel(const float* __restrict__ na, int N) {
    int idx = blockIdx.x * blockDim.x + threadIdx.x;
    int n = idx >> 6, j = idx & 63;
    if (n >= N) return;
    const float* b = na + (size_t)n * 256;
    float s = b[j];
    g_sn[n * 64 + j] = s;
    g_f0n[n * 128 + j] = s;
    float nn = 0.f;
#pragma unroll
    for (int c = 0; c < 3; c++) {
        float x = b[64 + 3 * j + c];
        g_xv[(size_t)c * NPLANE + n * 64 + j] = x;
        nn += x * x;
    }
    g_f0n[n * 128 + 64 + j] = sqrtf(nn);
}

__global__ void gate_node_kernel(int N) {
    int idx = blockIdx.x * blockDim.x + threadIdx.x;
    int n = idx >> 6, j = idx & 63;
    if (n >= N) return;
    float ga = g_g[n * 128 + 64 + j];
#pragma unroll
    for (int c = 0; c < 3; c++)
        g_hvg[(size_t)c * NPLANE + n * 64 + j] = g_xv[(size_t)c * NPLANE + n * 64 + j] * ga;
}

// s0 = [na0_s[dst], na0_s[src], ip/3]; t8 = ssp(edge_attr @ feW1 / sqrt(32))
__global__ void gather_kernel(const float* __restrict__ ea, const int* __restrict__ ei,
                              const float* __restrict__ feW1, int E) {
    int idx = blockIdx.x * blockDim.x + threadIdx.x;
    int e = idx >> 6, j = idx & 63;
    if (e >= E) return;
    int dst = ei[e], src = ei[E + e];
    g_s0[(size_t)e * 192 + j] = g_na0s[dst * 64 + j];
    g_s0[(size_t)e * 192 + 64 + j] = g_na0s[src * 64 + j];
    float ip = 0.f;
#pragma unroll
    for (int c = 0; c < 3; c++)
        ip += g_na0v[(size_t)c * NPLANE + dst * 64 + j] * g_na0v[(size_t)c * NPLANE + src * 64 + j];
    g_s0[(size_t)e * 192 + 128 + j] = ip * (1.f / 3.f);
    if (j < 8) {
        float a = 0.f;
        const float* er = ea + (size_t)e * 32;
#pragma unroll 8
        for (int k = 0; k < 32; k++) a += er[k] * feW1[k * 8 + j];
        g_t8[(size_t)e * 8 + j] = sspf(a * 0.17677669529663687f);
    }
}

// fe = t8 @ feW2 (unscaled; scale folded into Q3 auxScale)
__global__ void fe_kernel(const float* __restrict__ feW2, int E) {
    int idx = blockIdx.x * blockDim.x + threadIdx.x;
    int e = idx / 80, q = idx % 80;
    if (e >= E) return;
    float t[8];
#pragma unroll
    for (int i = 0; i < 8; i++) t[i] = g_t8[(size_t)e * 8 + i];
    int n0 = q * 4;
    float4 acc = make_float4(0.f, 0.f, 0.f, 0.f);
#pragma unroll
    for (int i = 0; i < 8; i++) {
        float4 wv = *(const float4*)&feW2[i * 320 + n0];
        acc.x += t[i] * wv.x; acc.y += t[i] * wv.y; acc.z += t[i] * wv.z; acc.w += t[i] * wv.w;
    }
    *(float4*)&g_fe[(size_t)e * 320 + n0] = acc;
}

// tensor product: f0e = [pair_s, |pair_v|], pv planes
__global__ void tp_kernel(const int* __restrict__ ei, int E) {
    int idx = blockIdx.x * blockDim.x + threadIdx.x;
    int e = idx >> 4, t = idx & 15;
    if (e >= E) return;
    int dst = ei[e], src = ei[E + e];
    const float C0 = 0.4472135954999579f, C1 = 0.7745966692414834f;
    const float IS3 = 0.5773502691896258f, IS6 = 0.4082482904638630f;
    const float* we = g_w + (size_t)e * 320;
#pragma unroll
    for (int k = 0; k < 4; k++) {
        int i = 4 * t + k;
        float xs = g_hs[src * 64 + i], ys = g_hs[dst * 64 + i];
        float xv0 = g_hv[0 * NPLANE + src * 64 + i], yv0 = g_hv[0 * NPLANE + dst * 64 + i];
        float xv1 = g_hv[1 * NPLANE + src * 64 + i], yv1 = g_hv[1 * NPLANE + dst * 64 + i];
        float xv2 = g_hv[2 * NPLANE + src * 64 + i], yv2 = g_hv[2 * NPLANE + dst * 64 + i];
        float ipv = xv0 * yv0 + xv1 * yv1 + xv2 * yv2;
        float psv = C0 * (we[i] * xs * ys + we[192 + i] * ipv * IS3);
        float cx = xv1 * yv2 - xv2 * yv1;
        float cy = xv2 * yv0 - xv0 * yv2;
        float cz = xv0 * yv1 - xv1 * yv0;
        float a011 = we[64 + i] * IS3 * C1;
        float a101 = we[128 + i] * IS3 * C1;
        float a111 = we[256 + i] * IS6 * C1;
        float p0 = a011 * xs * yv0 + a101 * xv0 * ys + a111 * cx;
        float p1 = a011 * xs * yv1 + a101 * xv1 * ys + a111 * cy;
        float p2 = a011 * xs * yv2 + a101 * xv2 * ys + a111 * cz;
        g_pv[0 * EPLANE + (size_t)e * 64 + i] = p0;
        g_pv[1 * EPLANE + (size_t)e * 64 + i] = p1;
        g_pv[2 * EPLANE + (size_t)e * 64 + i] = p2;
        g_f0e[(size_t)e * 128 + i] = psv;
        g_f0e[(size_t)e * 128 + 64 + i] = sqrtf(p0 * p0 + p1 * p1 + p2 * p2);
    }
}

__global__ void gate_edge_kernel(int E) {
    int idx = blockIdx.x * blockDim.x + threadIdx.x;
    int e = idx >> 6, j = idx & 63;
    if (e >= E) return;
    float ga = g_g2[(size_t)e * 128 + 64 + j];
#pragma unroll
    for (int c = 0; c < 3; c++)
        g_vg[(size_t)c * EPLANE + (size_t)e * 64 + j] = g_pv[(size_t)c * EPLANE + (size_t)e * 64 + j] * ga;
}

// ---------------- host ----------------

static void launch_gemm(const float* A, int lda, size_t aPlane,
                        const float* W, int ldw, const float* bias,
                        const float* aux, int auxLd, float auxScale,
                        const float* res,
                        float* out, int outLd, int colStride, int colOff, int zColStep, size_t outPlane,
                        int M, int K, int N, int planes, float alpha, int act)
{
    dim3 grid((M + BM - 1) / BM, N / BN, planes);
    gemm_kernel<<<grid, 256>>>(A, lda, aPlane, W, ldw, bias, aux, auxLd, auxScale, res,
                               out, outLd, colStride, colOff, zColStep, outPlane, M, K, alpha, act);
}

extern "C" void kernel_launch(void* const* d_in, const int* in_sizes, int n_in,
                              void* d_out, int out_size)
{
    const float* node_attr = (const float*)d_in[0];
    const float* edge_attr = (const float*)d_in[1];
    const float* npa       = (const float*)d_in[2];
    const float* Wi0 = (const float*)d_in[3];
    const float* bi0 = (const float*)d_in[4];
    const float* Wi1 = (const float*)d_in[5];
    const float* gpW1 = (const float*)d_in[6];
    const float* gpb1 = (const float*)d_in[7];
    const float* gpW2 = (const float*)d_in[8];
    const float* gpb2 = (const float*)d_in[9];
    const float* Wn0 = (const float*)d_in[10];
    const float* bn0 = (const float*)d_in[11];
    const float* Wn1 = (const float*)d_in[12];
    const float* feW1 = (const float*)d_in[13];
    const float* feW2 = (const float*)d_in[14];
    const float* fsW1 = (const float*)d_in[15];
    const float* fsb1 = (const float*)d_in[16];
    const float* fsW2 = (const float*)d_in[17];
    const float* fsb2 = (const float*)d_in[18];
    const float* gW1 = (const float*)d_in[19];
    const float* gb1 = (const float*)d_in[20];
    const float* gW2 = (const float*)d_in[21];
    const float* gb2 = (const float*)d_in[22];
    const float* Wo0 = (const float*)d_in[23];
    const float* bo0 = (const float*)d_in[24];
    const float* Wo1 = (const float*)d_in[25];
    const int*   ei  = (const int*)d_in[26];

    int N = in_sizes[0] / 256; if (N > MAXN) N = MAXN;
    int E = in_sizes[26] / 2;  if (E > MAXE) E = MAXE;
    float* out = (float*)d_out;

    float *sn, *xv, *f0n, *t1, *gg, *hvg, *na0s, *na0v, *hs, *hv;
    float *s0, *u, *fe, *w, *f0e, *pv, *t2, *g2, *vg;
    cudaGetSymbolAddress((void**)&sn, g_sn);   cudaGetSymbolAddress((void**)&xv, g_xv);
    cudaGetSymbolAddress((void**)&f0n, g_f0n); cudaGetSymbolAddress((void**)&t1, g_t1);
    cudaGetSymbolAddress((void**)&gg, g_g);    cudaGetSymbolAddress((void**)&hvg, g_hvg);
    cudaGetSymbolAddress((void**)&na0s, g_na0s); cudaGetSymbolAddress((void**)&na0v, g_na0v);
    cudaGetSymbolAddress((void**)&hs, g_hs);   cudaGetSymbolAddress((void**)&hv, g_hv);
    cudaGetSymbolAddress((void**)&s0, g_s0);   cudaGetSymbolAddress((void**)&u, g_u);
    cudaGetSymbolAddress((void**)&fe, g_fe);   cudaGetSymbolAddress((void**)&w, g_w);
    cudaGetSymbolAddress((void**)&f0e, g_f0e); cudaGetSymbolAddress((void**)&pv, g_pv);
    cudaGetSymbolAddress((void**)&t2, g_t2);   cudaGetSymbolAddress((void**)&g2, g_g2);
    cudaGetSymbolAddress((void**)&vg, g_vg);

    const float ISQ8 = 0.3535533905932738f;

    // ---- node pipeline ----
    prep_node_kernel<<<(N * 64 + 255) / 256, 256>>>(node_attr, N);
    launch_gemm(sn, 64, 0, Wi0, 64, bi0, 0, 0, 0.f, 0,
                na0s, 64, 1, 0, 0, 0, N, 64, 64, 1, 0.125f, 0);
    launch_gemm(xv, 64, NPLANE, Wi1, 64, 0, 0, 0, 0.f, 0,
                na0v, 64, 1, 0, 0, NPLANE, N, 64, 64, 3, 0.125f, 0);
    launch_gemm(f0n, 128, 0, gpW1, 128, gpb1, 0, 0, 0.f, 0,
                t1, 128, 1, 0, 0, 0, N, 128, 128, 1, 1.f, 1);
    launch_gemm(t1, 128, 0, gpW2, 128, gpb2, 0, 0, 0.f, 0,
                gg, 128, 1, 0, 0, 0, N, 128, 128, 1, 1.f, 0);
    gate_node_kernel<<<(N * 64 + 255) / 256, 256>>>(N);
    launch_gemm(gg, 128, 0, Wn0, 64, bn0, 0, 0, 0.f, 0,
                hs, 64, 1, 0, 0, 0, N, 64, 64, 1, 0.125f, 0);
    launch_gemm(hvg, 64, NPLANE, Wn1, 64, 0, 0, 0, 0.f, 0,
                hv, 64, 1, 0, 0, NPLANE, N, 64, 64, 3, 0.125f, 0);

    // ---- edge pipeline ----
    gather_kernel<<<(E * 64 + 255) / 256, 256>>>(edge_attr, ei, feW1, E);
    launch_gemm(s0, 192, 0, fsW1, 64, fsb1, 0, 0, 0.f, 0,
                u, 64, 1, 0, 0, 0, E, 192, 64, 1, 1.f, 1);
    fe_kernel<<<(E * 80 + 255) / 256, 256>>>(feW2, E);
    launch_gemm(u, 64, 0, fsW2, 320, fsb2, fe, 320, ISQ8, 0,
                w, 320, 1, 0, 0, 0, E, 64, 320, 1, 1.f, 0);
    tp_kernel<<<(E * 16 + 255) / 256, 256>>>(ei, E);
    launch_gemm(f0e, 128, 0, gW1, 128, gb1, 0, 0, 0.f, 0,
                t2, 128, 1, 0, 0, 0, E, 128, 128, 1, 1.f, 1);
    launch_gemm(t2, 128, 0, gW2, 128, gb2, 0, 0, 0.f, 0,
                g2, 128, 1, 0, 0, 0, E, 128, 128, 1, 1.f, 0);
    gate_edge_kernel<<<(E * 64 + 255) / 256, 256>>>(E);
    // out scalars: cols 0..63
    launch_gemm(g2, 128, 0, Wo0, 64, bo0, 0, 0, 0.f, npa,
                out, 256, 1, 0, 0, 0, E, 64, 64, 1, 0.125f, 0);
    // out vectors: cols 64 + 3n + z
    launch_gemm(vg, 64, EPLANE, Wo1, 64, 0, 0, 0, 0.f, npa,
                out, 256, 3, 64, 1, 0, E, 64, 64, 3, 0.125f, 0);
}

// round 5
// speedup vs baseline: 1.5230x; 1.0036x over previous
#include <cuda_runtime.h>
#include <math.h>

#define MAXN 20480
#define MAXE 122880
#define NPLANE ((size_t)MAXN * 64)
#define EPLANE ((size_t)MAXE * 64)

// ---------------- scratch (__device__, static) ----------------
// node side
__device__ float g_sn  [MAXN * 64];        // scalars of node_attr
__device__ float g_xv  [3 * MAXN * 64];    // vector planes of node_attr
__device__ float g_f0n [MAXN * 128];       // [s, |v|]
__device__ float g_t1  [MAXN * 128];
__device__ float g_g   [MAXN * 128];       // norm_gate MLP out
__device__ float g_hvg [3 * MAXN * 64];    // gated vectors
__device__ float g_na0s[MAXN * 64];
__device__ float g_na0v[3 * MAXN * 64];
__device__ float g_hs  [MAXN * 64];
__device__ float g_hv  [3 * MAXN * 64];
// edge side
__device__ float g_s0  [(size_t)MAXE * 192];
__device__ float g_t8  [(size_t)MAXE * 8];
__device__ float g_u   [(size_t)MAXE * 64];
__device__ float g_fe  [(size_t)MAXE * 320];
__device__ float g_w   [(size_t)MAXE * 320];
__device__ float g_f0e [(size_t)MAXE * 128];
__device__ float g_pv  [3 * (size_t)MAXE * 64];
__device__ float g_t2  [(size_t)MAXE * 128];
__device__ float g_g2  [(size_t)MAXE * 128];
__device__ float g_vg  [3 * (size_t)MAXE * 64];

__device__ __forceinline__ float siluf(float x) { return x * (1.f / (1.f + __expf(-x))); }
__device__ __forceinline__ float sspf(float x) {
    float sp = (x > 20.f) ? x : log1pf(__expf(x));
    return sp - 0.6931471805599453f;
}

// packed fp32x2 FMA (sm_103a)
#define FFMA2(d, a, b) asm("fma.rn.f32x2 %0, %1, %2, %0;" : "+l"(d) : "l"(a), "l"(b))

// ---------------- generic tiled GEMM ----------------
// C[row, n] = epilogue( alpha * sum_k A[row,k] * W[k,n] )
// block tile: 128 rows x 64 cols, BK=32. 256 threads, thread tile 8x4 via f32x2 pairs.
#define BM 128
#define BN 64
#define BK 32
#define AS_LD 132   // padded, 16B-aligned rows
#define WS_LD 136   // duplicated-pair weight rows, 16B-aligned

__global__ void __launch_bounds__(256) gemm_kernel(
    const float* __restrict__ A, int lda, size_t aPlane,
    const float* __restrict__ W, int ldw,
    const float* __restrict__ bias,
    const float* __restrict__ aux, int auxLd, float auxScale,
    const float* __restrict__ res,
    float* __restrict__ out, int outLd, int colStride, int colOff, int zColStep, size_t outPlane,
    int M, int K, float alpha, int act)
{
    __shared__ __align__(16) float As[BK * AS_LD];
    __shared__ __align__(16) float WsD[BK * WS_LD];

    const int z = blockIdx.z;
    A += (size_t)z * aPlane;
    out += (size_t)z * outPlane;
    const int cOff = colOff + z * zColStep;

    const int tid = threadIdx.x;
    const int tx = tid & 15;       // col group: 4 cols
    const int ty = tid >> 4;       // row group: 8 rows
    const int wid = tid >> 5, lane = tid & 31;
    const int rowBase = blockIdx.x * BM;
    const int nBase = blockIdx.y * BN;

    unsigned long long acc[4][4];
#pragma unroll
    for (int p = 0; p < 4; p++)
#pragma unroll
        for (int c = 0; c < 4; c++) acc[p][c] = 0ull;

    for (int k0 = 0; k0 < K; k0 += BK) {
        // fill A tile: As[k][m], warp wid loads 16 rows, lane = k
#pragma unroll 4
        for (int r = 0; r < 16; r++) {
            int mLoc = wid * 16 + r;
            int gRow = rowBase + mLoc;
            float v = 0.f;
            if (gRow < M) v = A[(size_t)gRow * lda + k0 + lane];
            As[lane * AS_LD + mLoc] = v;
        }
        // fill duplicated W tile
        for (int i = tid; i < BK * BN; i += 256) {
            int k = i >> 6, n = i & 63;
            float wv = W[(size_t)(k0 + k) * ldw + nBase + n];
            int o = k * WS_LD + 2 * n;
            WsD[o] = wv; WsD[o + 1] = wv;
        }
        __syncthreads();

#pragma unroll
        for (int k = 0; k < BK; k++) {
            const ulonglong2* ap = (const ulonglong2*)&As[k * AS_LD + ty * 8];
            ulonglong2 a0 = ap[0], a1 = ap[1];                 // row pairs (0,1)(2,3)(4,5)(6,7)
            const ulonglong2* wp = (const ulonglong2*)&WsD[k * WS_LD + tx * 8];
            ulonglong2 w0 = wp[0], w1 = wp[1];                 // dup cols c0,c1,c2,c3
            FFMA2(acc[0][0], a0.x, w0.x); FFMA2(acc[0][1], a0.x, w0.y);
            FFMA2(acc[0][2], a0.x, w1.x); FFMA2(acc[0][3], a0.x, w1.y);
            FFMA2(acc[1][0], a0.y, w0.x); FFMA2(acc[1][1], a0.y, w0.y);
            FFMA2(acc[1][2], a0.y, w1.x); FFMA2(acc[1][3], a0.y, w1.y);
            FFMA2(acc[2][0], a1.x, w0.x); FFMA2(acc[2][1], a1.x, w0.y);
            FFMA2(acc[2][2], a1.x, w1.x); FFMA2(acc[2][3], a1.x, w1.y);
            FFMA2(acc[3][0], a1.y, w0.x); FFMA2(acc[3][1], a1.y, w0.y);
            FFMA2(acc[3][2], a1.y, w1.x); FFMA2(acc[3][3], a1.y, w1.y);
        }
        __syncthreads();
    }

    // epilogue
#pragma unroll
    for (int p = 0; p < 4; p++) {
#pragma unroll
        for (int h = 0; h < 2; h++) {
            int row = rowBase + ty * 8 + 2 * p + h;
            if (row >= M) continue;
#pragma unroll
            for (int c = 0; c < 4; c++) {
                unsigned long long uacc = acc[p][c];
                float v = __uint_as_float(h == 0 ? (unsigned)uacc : (unsigned)(uacc >> 32));
                v *= alpha;
                int nG = nBase + tx * 4 + c;
                if (bias) v += bias[nG];
                if (act == 1) v = siluf(v);
                if (aux) v *= aux[(size_t)row * auxLd + nG] * auxScale;
                size_t oi = (size_t)row * outLd + cOff + (size_t)nG * colStride;
                if (res) v += res[oi];
                out[oi] = v;
            }
        }
    }
}

// ---------------- elementwise / gather kernels ----------------

__global__ void prep_node_kernel(const float* __restrict__ na, int N) {
    int idx = blockIdx.x * blockDim.x + threadIdx.x;
    int n = idx >> 6, j = idx & 63;
    if (n >= N) return;
    const float* b = na + (size_t)n * 256;
    float s = b[j];
    g_sn[n * 64 + j] = s;
    g_f0n[n * 128 + j] = s;
    float nn = 0.f;
#pragma unroll
    for (int c = 0; c < 3; c++) {
        float x = b[64 + 3 * j + c];
        g_xv[(size_t)c * NPLANE + n * 64 + j] = x;
        nn += x * x;
    }
    g_f0n[n * 128 + 64 + j] = sqrtf(nn);
}

__global__ void gate_node_kernel(int N) {
    int idx = blockIdx.x * blockDim.x + threadIdx.x;
    int n = idx >> 6, j = idx & 63;
    if (n >= N) return;
    float ga = g_g[n * 128 + 64 + j];
#pragma unroll
    for (int c = 0; c < 3; c++)
        g_hvg[(size_t)c * NPLANE + n * 64 + j] = g_xv[(size_t)c * NPLANE + n * 64 + j] * ga;
}

// s0 = [na0_s[dst], na0_s[src], ip/3]; t8 = ssp(edge_attr @ feW1 / sqrt(32))
__global__ void gather_kernel(const float* __restrict__ ea, const int* __restrict__ ei,
                              const float* __restrict__ feW1, int E) {
    int idx = blockIdx.x * blockDim.x + threadIdx.x;
    int e = idx >> 6, j = idx & 63;
    if (e >= E) return;
    int dst = ei[e], src = ei[E + e];
    g_s0[(size_t)e * 192 + j] = g_na0s[dst * 64 + j];
    g_s0[(size_t)e * 192 + 64 + j] = g_na0s[src * 64 + j];
    float ip = 0.f;
#pragma unroll
    for (int c = 0; c < 3; c++)
        ip += g_na0v[(size_t)c * NPLANE + dst * 64 + j] * g_na0v[(size_t)c * NPLANE + src * 64 + j];
    g_s0[(size_t)e * 192 + 128 + j] = ip * (1.f / 3.f);
    if (j < 8) {
        float a = 0.f;
        const float* er = ea + (size_t)e * 32;
#pragma unroll 8
        for (int k = 0; k < 32; k++) a += er[k] * feW1[k * 8 + j];
        g_t8[(size_t)e * 8 + j] = sspf(a * 0.17677669529663687f);
    }
}

// fe = t8 @ feW2 (unscaled; scale folded into Q3 auxScale)
__global__ void fe_kernel(const float* __restrict__ feW2, int E) {
    int idx = blockIdx.x * blockDim.x + threadIdx.x;
    int e = idx / 80, q = idx % 80;
    if (e >= E) return;
    float t[8];
#pragma unroll
    for (int i = 0; i < 8; i++) t[i] = g_t8[(size_t)e * 8 + i];
    int n0 = q * 4;
    float4 acc = make_float4(0.f, 0.f, 0.f, 0.f);
#pragma unroll
    for (int i = 0; i < 8; i++) {
        float4 wv = *(const float4*)&feW2[i * 320 + n0];
        acc.x += t[i] * wv.x; acc.y += t[i] * wv.y; acc.z += t[i] * wv.z; acc.w += t[i] * wv.w;
    }
    *(float4*)&g_fe[(size_t)e * 320 + n0] = acc;
}

// tensor product: f0e = [pair_s, |pair_v|], pv planes
__global__ void tp_kernel(const int* __restrict__ ei, int E) {
    int idx = blockIdx.x * blockDim.x + threadIdx.x;
    int e = idx >> 4, t = idx & 15;
    if (e >= E) return;
    int dst = ei[e], src = ei[E + e];
    const float C0 = 0.4472135954999579f, C1 = 0.7745966692414834f;
    const float IS3 = 0.5773502691896258f, IS6 = 0.4082482904638630f;
    const float* we = g_w + (size_t)e * 320;
#pragma unroll
    for (int k = 0; k < 4; k++) {
        int i = 4 * t + k;
        float xs = g_hs[src * 64 + i], ys = g_hs[dst * 64 + i];
        float xv0 = g_hv[0 * NPLANE + src * 64 + i], yv0 = g_hv[0 * NPLANE + dst * 64 + i];
        float xv1 = g_hv[1 * NPLANE + src * 64 + i], yv1 = g_hv[1 * NPLANE + dst * 64 + i];
        float xv2 = g_hv[2 * NPLANE + src * 64 + i], yv2 = g_hv[2 * NPLANE + dst * 64 + i];
        float ipv = xv0 * yv0 + xv1 * yv1 + xv2 * yv2;
        float psv = C0 * (we[i] * xs * ys + we[192 + i] * ipv * IS3);
        float cx = xv1 * yv2 - xv2 * yv1;
        float cy = xv2 * yv0 - xv0 * yv2;
        float cz = xv0 * yv1 - xv1 * yv0;
        float a011 = we[64 + i] * IS3 * C1;
        float a101 = we[128 + i] * IS3 * C1;
        float a111 = we[256 + i] * IS6 * C1;
        float p0 = a011 * xs * yv0 + a101 * xv0 * ys + a111 * cx;
        float p1 = a011 * xs * yv1 + a101 * xv1 * ys + a111 * cy;
        float p2 = a011 * xs * yv2 + a101 * xv2 * ys + a111 * cz;
        g_pv[0 * EPLANE + (size_t)e * 64 + i] = p0;
        g_pv[1 * EPLANE + (size_t)e * 64 + i] = p1;
        g_pv[2 * EPLANE + (size_t)e * 64 + i] = p2;
        g_f0e[(size_t)e * 128 + i] = psv;
        g_f0e[(size_t)e * 128 + 64 + i] = sqrtf(p0 * p0 + p1 * p1 + p2 * p2);
    }
}

__global__ void gate_edge_kernel(int E) {
    int idx = blockIdx.x * blockDim.x + threadIdx.x;
    int e = idx >> 6, j = idx & 63;
    if (e >= E) return;
    float ga = g_g2[(size_t)e * 128 + 64 + j];
#pragma unroll
    for (int c = 0; c < 3; c++)
        g_vg[(size_t)c * EPLANE + (size_t)e * 64 + j] = g_pv[(size_t)c * EPLANE + (size_t)e * 64 + j] * ga;
}

// ---------------- host ----------------

static void launch_gemm(const float* A, int lda, size_t aPlane,
                        const float* W, int ldw, const float* bias,
                        const float* aux, int auxLd, float auxScale,
                        const float* res,
                        float* out, int outLd, int colStride, int colOff, int zColStep, size_t outPlane,
                        int M, int K, int N, int planes, float alpha, int act)
{
    dim3 grid((M + BM - 1) / BM, N / BN, planes);
    gemm_kernel<<<grid, 256>>>(A, lda, aPlane, W, ldw, bias, aux, auxLd, auxScale, res,
                               out, outLd, colStride, colOff, zColStep, outPlane, M, K, alpha, act);
}

extern "C" void kernel_launch(void* const* d_in, const int* in_sizes, int n_in,
                              void* d_out, int out_size)
{
    const float* node_attr = (const float*)d_in[0];
    const float* edge_attr = (const float*)d_in[1];
    const float* npa       = (const float*)d_in[2];
    const float* Wi0 = (const float*)d_in[3];
    const float* bi0 = (const float*)d_in[4];
    const float* Wi1 = (const float*)d_in[5];
    const float* gpW1 = (const float*)d_in[6];
    const float* gpb1 = (const float*)d_in[7];
    const float* gpW2 = (const float*)d_in[8];
    const float* gpb2 = (const float*)d_in[9];
    const float* Wn0 = (const float*)d_in[10];
    const float* bn0 = (const float*)d_in[11];
    const float* Wn1 = (const float*)d_in[12];
    const float* feW1 = (const float*)d_in[13];
    const float* feW2 = (const float*)d_in[14];
    const float* fsW1 = (const float*)d_in[15];
    const float* fsb1 = (const float*)d_in[16];
    const float* fsW2 = (const float*)d_in[17];
    const float* fsb2 = (const float*)d_in[18];
    const float* gW1 = (const float*)d_in[19];
    const float* gb1 = (const float*)d_in[20];
    const float* gW2 = (const float*)d_in[21];
    const float* gb2 = (const float*)d_in[22];
    const float* Wo0 = (const float*)d_in[23];
    const float* bo0 = (const float*)d_in[24];
    const float* Wo1 = (const float*)d_in[25];
    const int*   ei  = (const int*)d_in[26];

    int N = in_sizes[0] / 256; if (N > MAXN) N = MAXN;
    int E = in_sizes[26] / 2;  if (E > MAXE) E = MAXE;
    float* out = (float*)d_out;

    float *sn, *xv, *f0n, *t1, *gg, *hvg, *na0s, *na0v, *hs, *hv;
    float *s0, *u, *fe, *w, *f0e, *pv, *t2, *g2, *vg;
    cudaGetSymbolAddress((void**)&sn, g_sn);   cudaGetSymbolAddress((void**)&xv, g_xv);
    cudaGetSymbolAddress((void**)&f0n, g_f0n); cudaGetSymbolAddress((void**)&t1, g_t1);
    cudaGetSymbolAddress((void**)&gg, g_g);    cudaGetSymbolAddress((void**)&hvg, g_hvg);
    cudaGetSymbolAddress((void**)&na0s, g_na0s); cudaGetSymbolAddress((void**)&na0v, g_na0v);
    cudaGetSymbolAddress((void**)&hs, g_hs);   cudaGetSymbolAddress((void**)&hv, g_hv);
    cudaGetSymbolAddress((void**)&s0, g_s0);   cudaGetSymbolAddress((void**)&u, g_u);
    cudaGetSymbolAddress((void**)&fe, g_fe);   cudaGetSymbolAddress((void**)&w, g_w);
    cudaGetSymbolAddress((void**)&f0e, g_f0e); cudaGetSymbolAddress((void**)&pv, g_pv);
    cudaGetSymbolAddress((void**)&t2, g_t2);   cudaGetSymbolAddress((void**)&g2, g_g2);
    cudaGetSymbolAddress((void**)&vg, g_vg);

    const float ISQ8 = 0.3535533905932738f;

    // ---- node pipeline ----
    prep_node_kernel<<<(N * 64 + 255) / 256, 256>>>(node_attr, N);
    launch_gemm(sn, 64, 0, Wi0, 64, bi0, 0, 0, 0.f, 0,
                na0s, 64, 1, 0, 0, 0, N, 64, 64, 1, 0.125f, 0);
    launch_gemm(xv, 64, NPLANE, Wi1, 64, 0, 0, 0, 0.f, 0,
                na0v, 64, 1, 0, 0, NPLANE, N, 64, 64, 3, 0.125f, 0);
    launch_gemm(f0n, 128, 0, gpW1, 128, gpb1, 0, 0, 0.f, 0,
                t1, 128, 1, 0, 0, 0, N, 128, 128, 1, 1.f, 1);
    launch_gemm(t1, 128, 0, gpW2, 128, gpb2, 0, 0, 0.f, 0,
                gg, 128, 1, 0, 0, 0, N, 128, 128, 1, 1.f, 0);
    gate_node_kernel<<<(N * 64 + 255) / 256, 256>>>(N);
    launch_gemm(gg, 128, 0, Wn0, 64, bn0, 0, 0, 0.f, 0,
                hs, 64, 1, 0, 0, 0, N, 64, 64, 1, 0.125f, 0);
    launch_gemm(hvg, 64, NPLANE, Wn1, 64, 0, 0, 0, 0.f, 0,
                hv, 64, 1, 0, 0, NPLANE, N, 64, 64, 3, 0.125f, 0);

    // ---- edge pipeline ----
    gather_kernel<<<(E * 64 + 255) / 256, 256>>>(edge_attr, ei, feW1, E);
    launch_gemm(s0, 192, 0, fsW1, 64, fsb1, 0, 0, 0.f, 0,
                u, 64, 1, 0, 0, 0, E, 192, 64, 1, 1.f, 1);
    fe_kernel<<<(E * 80 + 255) / 256, 256>>>(feW2, E);
    launch_gemm(u, 64, 0, fsW2, 320, fsb2, fe, 320, ISQ8, 0,
                w, 320, 1, 0, 0, 0, E, 64, 320, 1, 1.f, 0);
    tp_kernel<<<(E * 16 + 255) / 256, 256>>>(ei, E);
    launch_gemm(f0e, 128, 0, gW1, 128, gb1, 0, 0, 0.f, 0,
                t2, 128, 1, 0, 0, 0, E, 128, 128, 1, 1.f, 1);
    launch_gemm(t2, 128, 0, gW2, 128, gb2, 0, 0, 0.f, 0,
                g2, 128, 1, 0, 0, 0, E, 128, 128, 1, 1.f, 0);
    gate_edge_kernel<<<(E * 64 + 255) / 256, 256>>>(E);
    // out scalars: cols 0..63
    launch_gemm(g2, 128, 0, Wo0, 64, bo0, 0, 0, 0.f, npa,
                out, 256, 1, 0, 0, 0, E, 64, 64, 1, 0.125f, 0);
    // out vectors: cols 64 + 3n + z
    launch_gemm(vg, 64, EPLANE, Wo1, 64, 0, 0, 0, 0.f, npa,
                out, 256, 3, 64, 1, 0, E, 64, 64, 3, 0.125f, 0);
}

// round 6
// speedup vs baseline: 1.5247x; 1.0011x over previous
#include <cuda_runtime.h>
#include <math.h>

#define MAXN 20480
#define MAXE 122880
#define NPLANE ((size_t)MAXN * 64)
#define EPLANE ((size_t)MAXE * 64)

// ---------------- scratch (__device__, static) ----------------
// node side
__device__ float g_sn  [MAXN * 64];        // scalars of node_attr
__device__ float g_xv  [3 * MAXN * 64];    // vector planes of node_attr
__device__ float g_f0n [MAXN * 128];       // [s, |v|]
__device__ float g_t1  [MAXN * 128];
__device__ float g_g   [MAXN * 128];       // norm_gate MLP out
__device__ float g_hvg [3 * MAXN * 64];    // gated vectors
__device__ float g_na0s[MAXN * 64];
__device__ float g_na0v[3 * MAXN * 64];
__device__ float g_hs  [MAXN * 64];
__device__ float g_hv  [3 * MAXN * 64];
// edge side
__device__ float g_s0  [(size_t)MAXE * 192];
__device__ float g_t8  [(size_t)MAXE * 8];
__device__ float g_u   [(size_t)MAXE * 64];
__device__ float g_fe  [(size_t)MAXE * 320];
__device__ float g_w   [(size_t)MAXE * 320];
__device__ float g_f0e [(size_t)MAXE * 128];
__device__ float g_pv  [3 * (size_t)MAXE * 64];
__device__ float g_t2  [(size_t)MAXE * 128];
__device__ float g_g2  [(size_t)MAXE * 128];
__device__ float g_vg  [3 * (size_t)MAXE * 64];

__device__ __forceinline__ float siluf(float x) { return x * (1.f / (1.f + __expf(-x))); }
__device__ __forceinline__ float sspf(float x) {
    float sp = (x > 20.f) ? x : log1pf(__expf(x));
    return sp - 0.6931471805599453f;
}

// packed fp32x2 FMA (sm_103a)
#define FFMA2(d, a, b) asm("fma.rn.f32x2 %0, %1, %2, %0;" : "+l"(d) : "l"(a), "l"(b))

// ---------------- generic tiled GEMM ----------------
// C[row, n] = epilogue( alpha * sum_k A[row,k] * W[k,n] )
// block tile: 128 rows x 64 cols, BK=32. 256 threads, thread tile 8x4 via f32x2 pairs.
#define BM 128
#define BN 64
#define BK 32
#define AS_LD 132   // padded, 16B-aligned rows
#define WS_LD 136   // duplicated-pair weight rows, 16B-aligned

__global__ void __launch_bounds__(256) gemm_kernel(
    const float* __restrict__ A, int lda, size_t aPlane,
    const float* __restrict__ W, int ldw,
    const float* __restrict__ bias,
    const float* __restrict__ aux, int auxLd, float auxScale,
    const float* __restrict__ res,
    float* __restrict__ out, int outLd, int colStride, int colOff, int zColStep, size_t outPlane,
    int M, int K, float alpha, int act)
{
    __shared__ __align__(16) float As[BK * AS_LD];
    __shared__ __align__(16) float WsD[BK * WS_LD];

    const int z = blockIdx.z;
    A += (size_t)z * aPlane;
    out += (size_t)z * outPlane;
    const int cOff = colOff + z * zColStep;

    const int tid = threadIdx.x;
    const int tx = tid & 15;       // col group: 4 cols
    const int ty = tid >> 4;       // row group: 8 rows
    const int wid = tid >> 5, lane = tid & 31;
    const int rowBase = blockIdx.x * BM;
    const int nBase = blockIdx.y * BN;

    unsigned long long acc[4][4];
#pragma unroll
    for (int p = 0; p < 4; p++)
#pragma unroll
        for (int c = 0; c < 4; c++) acc[p][c] = 0ull;

    for (int k0 = 0; k0 < K; k0 += BK) {
        // fill A tile: As[k][m], warp wid loads 16 rows, lane = k
#pragma unroll 4
        for (int r = 0; r < 16; r++) {
            int mLoc = wid * 16 + r;
            int gRow = rowBase + mLoc;
            float v = 0.f;
            if (gRow < M) v = A[(size_t)gRow * lda + k0 + lane];
            As[lane * AS_LD + mLoc] = v;
        }
        // fill duplicated W tile
        for (int i = tid; i < BK * BN; i += 256) {
            int k = i >> 6, n = i & 63;
            float wv = W[(size_t)(k0 + k) * ldw + nBase + n];
            int o = k * WS_LD + 2 * n;
            WsD[o] = wv; WsD[o + 1] = wv;
        }
        __syncthreads();

#pragma unroll
        for (int k = 0; k < BK; k++) {
            const ulonglong2* ap = (const ulonglong2*)&As[k * AS_LD + ty * 8];
            ulonglong2 a0 = ap[0], a1 = ap[1];                 // row pairs (0,1)(2,3)(4,5)(6,7)
            const ulonglong2* wp = (const ulonglong2*)&WsD[k * WS_LD + tx * 8];
            ulonglong2 w0 = wp[0], w1 = wp[1];                 // dup cols c0,c1,c2,c3
            FFMA2(acc[0][0], a0.x, w0.x); FFMA2(acc[0][1], a0.x, w0.y);
            FFMA2(acc[0][2], a0.x, w1.x); FFMA2(acc[0][3], a0.x, w1.y);
            FFMA2(acc[1][0], a0.y, w0.x); FFMA2(acc[1][1], a0.y, w0.y);
            FFMA2(acc[1][2], a0.y, w1.x); FFMA2(acc[1][3], a0.y, w1.y);
            FFMA2(acc[2][0], a1.x, w0.x); FFMA2(acc[2][1], a1.x, w0.y);
            FFMA2(acc[2][2], a1.x, w1.x); FFMA2(acc[2][3], a1.x, w1.y);
            FFMA2(acc[3][0], a1.y, w0.x); FFMA2(acc[3][1], a1.y, w0.y);
            FFMA2(acc[3][2], a1.y, w1.x); FFMA2(acc[3][3], a1.y, w1.y);
        }
        __syncthreads();
    }

    // epilogue
#pragma unroll
    for (int p = 0; p < 4; p++) {
#pragma unroll
        for (int h = 0; h < 2; h++) {
            int row = rowBase + ty * 8 + 2 * p + h;
            if (row >= M) continue;
#pragma unroll
            for (int c = 0; c < 4; c++) {
                unsigned long long uacc = acc[p][c];
                float v = __uint_as_float(h == 0 ? (unsigned)uacc : (unsigned)(uacc >> 32));
                v *= alpha;
                int nG = nBase + tx * 4 + c;
                if (bias) v += bias[nG];
                if (act == 1) v = siluf(v);
                if (aux) v *= aux[(size_t)row * auxLd + nG] * auxScale;
                size_t oi = (size_t)row * outLd + cOff + (size_t)nG * colStride;
                if (res) v += res[oi];
                out[oi] = v;
            }
        }
    }
}

// ---------------- elementwise / gather kernels ----------------

__global__ void prep_node_kernel(const float* __restrict__ na, int N) {
    int idx = blockIdx.x * blockDim.x + threadIdx.x;
    int n = idx >> 6, j = idx & 63;
    if (n >= N) return;
    const float* b = na + (size_t)n * 256;
    float s = b[j];
    g_sn[n * 64 + j] = s;
    g_f0n[n * 128 + j] = s;
    float nn = 0.f;
#pragma unroll
    for (int c = 0; c < 3; c++) {
        float x = b[64 + 3 * j + c];
        g_xv[(size_t)c * NPLANE + n * 64 + j] = x;
        nn += x * x;
    }
    g_f0n[n * 128 + 64 + j] = sqrtf(nn);
}

__global__ void gate_node_kernel(int N) {
    int idx = blockIdx.x * blockDim.x + threadIdx.x;
    int n = idx >> 6, j = idx & 63;
    if (n >= N) return;
    float ga = g_g[n * 128 + 64 + j];
#pragma unroll
    for (int c = 0; c < 3; c++)
        g_hvg[(size_t)c * NPLANE + n * 64 + j] = g_xv[(size_t)c * NPLANE + n * 64 + j] * ga;
}

// s0 = [na0_s[dst], na0_s[src], ip/3]; t8 = ssp(edge_attr @ feW1 / sqrt(32))
__global__ void gather_kernel(const float* __restrict__ ea, const int* __restrict__ ei,
                              const float* __restrict__ feW1, int E) {
    int idx = blockIdx.x * blockDim.x + threadIdx.x;
    int e = idx >> 6, j = idx & 63;
    if (e >= E) return;
    int dst = ei[e], src = ei[E + e];
    g_s0[(size_t)e * 192 + j] = g_na0s[dst * 64 + j];
    g_s0[(size_t)e * 192 + 64 + j] = g_na0s[src * 64 + j];
    float ip = 0.f;
#pragma unroll
    for (int c = 0; c < 3; c++)
        ip += g_na0v[(size_t)c * NPLANE + dst * 64 + j] * g_na0v[(size_t)c * NPLANE + src * 64 + j];
    g_s0[(size_t)e * 192 + 128 + j] = ip * (1.f / 3.f);
    if (j < 8) {
        float a = 0.f;
        const float* er = ea + (size_t)e * 32;
#pragma unroll 8
        for (int k = 0; k < 32; k++) a += er[k] * feW1[k * 8 + j];
        g_t8[(size_t)e * 8 + j] = sspf(a * 0.17677669529663687f);
    }
}

// fe = t8 @ feW2 (unscaled; scale folded into Q3 auxScale)
__global__ void fe_kernel(const float* __restrict__ feW2, int E) {
    int idx = blockIdx.x * blockDim.x + threadIdx.x;
    int e = idx / 80, q = idx % 80;
    if (e >= E) return;
    float t[8];
#pragma unroll
    for (int i = 0; i < 8; i++) t[i] = g_t8[(size_t)e * 8 + i];
    int n0 = q * 4;
    float4 acc = make_float4(0.f, 0.f, 0.f, 0.f);
#pragma unroll
    for (int i = 0; i < 8; i++) {
        float4 wv = *(const float4*)&feW2[i * 320 + n0];
        acc.x += t[i] * wv.x; acc.y += t[i] * wv.y; acc.z += t[i] * wv.z; acc.w += t[i] * wv.w;
    }
    *(float4*)&g_fe[(size_t)e * 320 + n0] = acc;
}

// tensor product: f0e = [pair_s, |pair_v|], pv planes
__global__ void tp_kernel(const int* __restrict__ ei, int E) {
    int idx = blockIdx.x * blockDim.x + threadIdx.x;
    int e = idx >> 4, t = idx & 15;
    if (e >= E) return;
    int dst = ei[e], src = ei[E + e];
    const float C0 = 0.4472135954999579f, C1 = 0.7745966692414834f;
    const float IS3 = 0.5773502691896258f, IS6 = 0.4082482904638630f;
    const float* we = g_w + (size_t)e * 320;
#pragma unroll
    for (int k = 0; k < 4; k++) {
        int i = 4 * t + k;
        float xs = g_hs[src * 64 + i], ys = g_hs[dst * 64 + i];
        float xv0 = g_hv[0 * NPLANE + src * 64 + i], yv0 = g_hv[0 * NPLANE + dst * 64 + i];
        float xv1 = g_hv[1 * NPLANE + src * 64 + i], yv1 = g_hv[1 * NPLANE + dst * 64 + i];
        float xv2 = g_hv[2 * NPLANE + src * 64 + i], yv2 = g_hv[2 * NPLANE + dst * 64 + i];
        float ipv = xv0 * yv0 + xv1 * yv1 + xv2 * yv2;
        float psv = C0 * (we[i] * xs * ys + we[192 + i] * ipv * IS3);
        float cx = xv1 * yv2 - xv2 * yv1;
        float cy = xv2 * yv0 - xv0 * yv2;
        float cz = xv0 * yv1 - xv1 * yv0;
        float a011 = we[64 + i] * IS3 * C1;
        float a101 = we[128 + i] * IS3 * C1;
        float a111 = we[256 + i] * IS6 * C1;
        float p0 = a011 * xs * yv0 + a101 * xv0 * ys + a111 * cx;
        float p1 = a011 * xs * yv1 + a101 * xv1 * ys + a111 * cy;
        float p2 = a011 * xs * yv2 + a101 * xv2 * ys + a111 * cz;
        g_pv[0 * EPLANE + (size_t)e * 64 + i] = p0;
        g_pv[1 * EPLANE + (size_t)e * 64 + i] = p1;
        g_pv[2 * EPLANE + (size_t)e * 64 + i] = p2;
        g_f0e[(size_t)e * 128 + i] = psv;
        g_f0e[(size_t)e * 128 + 64 + i] = sqrtf(p0 * p0 + p1 * p1 + p2 * p2);
    }
}

__global__ void gate_edge_kernel(int E) {
    int idx = blockIdx.x * blockDim.x + threadIdx.x;
    int e = idx >> 6, j = idx & 63;
    if (e >= E) return;
    float ga = g_g2[(size_t)e * 128 + 64 + j];
#pragma unroll
    for (int c = 0; c < 3; c++)
        g_vg[(size_t)c * EPLANE + (size_t)e * 64 + j] = g_pv[(size_t)c * EPLANE + (size_t)e * 64 + j] * ga;
}

// ---------------- host ----------------

static void launch_gemm(const float* A, int lda, size_t aPlane,
                        const float* W, int ldw, const float* bias,
                        const float* aux, int auxLd, float auxScale,
                        const float* res,
                        float* out, int outLd, int colStride, int colOff, int zColStep, size_t outPlane,
                        int M, int K, int N, int planes, float alpha, int act)
{
    dim3 grid((M + BM - 1) / BM, N / BN, planes);
    gemm_kernel<<<grid, 256>>>(A, lda, aPlane, W, ldw, bias, aux, auxLd, auxScale, res,
                               out, outLd, colStride, colOff, zColStep, outPlane, M, K, alpha, act);
}

extern "C" void kernel_launch(void* const* d_in, const int* in_sizes, int n_in,
                              void* d_out, int out_size)
{
    const float* node_attr = (const float*)d_in[0];
    const float* edge_attr = (const float*)d_in[1];
    const float* npa       = (const float*)d_in[2];
    const float* Wi0 = (const float*)d_in[3];
    const float* bi0 = (const float*)d_in[4];
    const float* Wi1 = (const float*)d_in[5];
    const float* gpW1 = (const float*)d_in[6];
    const float* gpb1 = (const float*)d_in[7];
    const float* gpW2 = (const float*)d_in[8];
    const float* gpb2 = (const float*)d_in[9];
    const float* Wn0 = (const float*)d_in[10];
    const float* bn0 = (const float*)d_in[11];
    const float* Wn1 = (const float*)d_in[12];
    const float* feW1 = (const float*)d_in[13];
    const float* feW2 = (const float*)d_in[14];
    const float* fsW1 = (const float*)d_in[15];
    const float* fsb1 = (const float*)d_in[16];
    const float* fsW2 = (const float*)d_in[17];
    const float* fsb2 = (const float*)d_in[18];
    const float* gW1 = (const float*)d_in[19];
    const float* gb1 = (const float*)d_in[20];
    const float* gW2 = (const float*)d_in[21];
    const float* gb2 = (const float*)d_in[22];
    const float* Wo0 = (const float*)d_in[23];
    const float* bo0 = (const float*)d_in[24];
    const float* Wo1 = (const float*)d_in[25];
    const int*   ei  = (const int*)d_in[26];

    int N = in_sizes[0] / 256; if (N > MAXN) N = MAXN;
    int E = in_sizes[26] / 2;  if (E > MAXE) E = MAXE;
    float* out = (float*)d_out;

    float *sn, *xv, *f0n, *t1, *gg, *hvg, *na0s, *na0v, *hs, *hv;
    float *s0, *u, *fe, *w, *f0e, *pv, *t2, *g2, *vg;
    cudaGetSymbolAddress((void**)&sn, g_sn);   cudaGetSymbolAddress((void**)&xv, g_xv);
    cudaGetSymbolAddress((void**)&f0n, g_f0n); cudaGetSymbolAddress((void**)&t1, g_t1);
    cudaGetSymbolAddress((void**)&gg, g_g);    cudaGetSymbolAddress((void**)&hvg, g_hvg);
    cudaGetSymbolAddress((void**)&na0s, g_na0s); cudaGetSymbolAddress((void**)&na0v, g_na0v);
    cudaGetSymbolAddress((void**)&hs, g_hs);   cudaGetSymbolAddress((void**)&hv, g_hv);
    cudaGetSymbolAddress((void**)&s0, g_s0);   cudaGetSymbolAddress((void**)&u, g_u);
    cudaGetSymbolAddress((void**)&fe, g_fe);   cudaGetSymbolAddress((void**)&w, g_w);
    cudaGetSymbolAddress((void**)&f0e, g_f0e); cudaGetSymbolAddress((void**)&pv, g_pv);
    cudaGetSymbolAddress((void**)&t2, g_t2);   cudaGetSymbolAddress((void**)&g2, g_g2);
    cudaGetSymbolAddress((void**)&vg, g_vg);

    const float ISQ8 = 0.3535533905932738f;

    // ---- node pipeline ----
    prep_node_kernel<<<(N * 64 + 255) / 256, 256>>>(node_attr, N);
    launch_gemm(sn, 64, 0, Wi0, 64, bi0, 0, 0, 0.f, 0,
                na0s, 64, 1, 0, 0, 0, N, 64, 64, 1, 0.125f, 0);
    launch_gemm(xv, 64, NPLANE, Wi1, 64, 0, 0, 0, 0.f, 0,
                na0v, 64, 1, 0, 0, NPLANE, N, 64, 64, 3, 0.125f, 0);
    launch_gemm(f0n, 128, 0, gpW1, 128, gpb1, 0, 0, 0.f, 0,
                t1, 128, 1, 0, 0, 0, N, 128, 128, 1, 1.f, 1);
    launch_gemm(t1, 128, 0, gpW2, 128, gpb2, 0, 0, 0.f, 0,
                gg, 128, 1, 0, 0, 0, N, 128, 128, 1, 1.f, 0);
    gate_node_kernel<<<(N * 64 + 255) / 256, 256>>>(N);
    launch_gemm(gg, 128, 0, Wn0, 64, bn0, 0, 0, 0.f, 0,
                hs, 64, 1, 0, 0, 0, N, 64, 64, 1, 0.125f, 0);
    launch_gemm(hvg, 64, NPLANE, Wn1, 64, 0, 0, 0, 0.f, 0,
                hv, 64, 1, 0, 0, NPLANE, N, 64, 64, 3, 0.125f, 0);

    // ---- edge pipeline ----
    gather_kernel<<<(E * 64 + 255) / 256, 256>>>(edge_attr, ei, feW1, E);
    launch_gemm(s0, 192, 0, fsW1, 64, fsb1, 0, 0, 0.f, 0,
                u, 64, 1, 0, 0, 0, E, 192, 64, 1, 1.f, 1);
    fe_kernel<<<(E * 80 + 255) / 256, 256>>>(feW2, E);
    launch_gemm(u, 64, 0, fsW2, 320, fsb2, fe, 320, ISQ8, 0,
                w, 320, 1, 0, 0, 0, E, 64, 320, 1, 1.f, 0);
    tp_kernel<<<(E * 16 + 255) / 256, 256>>>(ei, E);
    launch_gemm(f0e, 128, 0, gW1, 128, gb1, 0, 0, 0.f, 0,
                t2, 128, 1, 0, 0, 0, E, 128, 128, 1, 1.f, 1);
    launch_gemm(t2, 128, 0, gW2, 128, gb2, 0, 0, 0.f, 0,
                g2, 128, 1, 0, 0, 0, E, 128, 128, 1, 1.f, 0);
    gate_edge_kernel<<<(E * 64 + 255) / 256, 256>>>(E);
    // out scalars: cols 0..63
    launch_gemm(g2, 128, 0, Wo0, 64, bo0, 0, 0, 0.f, npa,
                out, 256, 1, 0, 0, 0, E, 64, 64, 1, 0.125f, 0);
    // out vectors: cols 64 + 3n + z
    launch_gemm(vg, 64, EPLANE, Wo1, 64, 0, 0, 0, 0.f, npa,
                out, 256, 3, 64, 1, 0, E, 64, 64, 3, 0.125f, 0);
}